// round 3
// baseline (speedup 1.0000x reference)
#include <cuda_runtime.h>

// Problem constants
#define Bn 8
#define Cn 64
#define Hn 128
#define Wn 128
#define HWn (Hn * Wn)

// Scratch: per-pixel sum of squares of fused over channels (512 KB)
__device__ float g_ss[Bn * HWn];

// ---------------------------------------------------------------------------
// Kernel 1: SS[b,h,w] = sum_c fused[b,c,h,w]^2
// ---------------------------------------------------------------------------
__global__ __launch_bounds__(256) void ss_kernel(const float* __restrict__ fused) {
    int p = blockIdx.x * blockDim.x + threadIdx.x;      // 0 .. B*HW-1
    int b = p >> 14;
    int pos = p & (HWn - 1);
    const float* ptr = fused + (size_t)b * Cn * HWn + pos;
    float s = 0.f;
#pragma unroll 16
    for (int c = 0; c < Cn; c++) {
        float v = ptr[c * HWn];
        s = fmaf(v, v, s);
    }
    g_ss[p] = s;
}

// ---------------------------------------------------------------------------
// Kernel 2: main refine with 4-way channel split.
// A quad of warps owns 64 consecutive w of one (b,h) row (2 px/thread,
// float2). Warp `half` in the quad accumulates channels [half*16, half*16+16).
// Partials combine through padded smem; all four warps compute the softmax
// redundantly, then each runs pass 2 on its own 16 channels.
// ---------------------------------------------------------------------------
__global__ __launch_bounds__(256) void refine_kernel(const float* __restrict__ fe,
                                                     const float* __restrict__ fused,
                                                     float* __restrict__ out) {
    __shared__ float red[8][32][21];   // [warp][lane][18 ax + 2 sf], pad 21

    const int lane    = threadIdx.x & 31;
    const int wid     = threadIdx.x >> 5;
    const int groupId = blockIdx.x * 2 + (wid >> 2);  // 0 .. 2047
    const int half    = wid & 3;                       // channel quarter
    const int seg     = groupId & 1;                   // which 64-wide half row
    const int h       = (groupId >> 1) & (Hn - 1);
    const int b       = groupId >> 8;
    const int w0      = seg * 64 + lane * 2;
    const int c0      = half * 16;

    const size_t bOff = (size_t)b * Cn * HWn;
    const float* feB  = fe    + bOff + (size_t)c0 * HWn + h * Wn + w0;
    const float* fuB  = fused + bOff + (size_t)c0 * HWn + w0;
    float*       outB = out   + bOff + (size_t)c0 * HWn + h * Wn + w0;

    const bool up = (h > 0), dn = (h < Hn - 1);
    const bool lEdge = (lane == 0), rEdge = (lane == 31);
    const bool lIn = (seg == 1);   // left neighbor exists (w0-1 >= 0)
    const bool rIn = (seg == 0);   // right neighbor exists (w0+2 <= 127)

    // partial cross-correlation accumulators: ax[k][px] = sum_c p_k * f
    float ax[9][2];
#pragma unroll
    for (int k = 0; k < 9; k++) { ax[k][0] = 0.f; ax[k][1] = 0.f; }
    float sf0 = 0.f, sf1 = 0.f;   // partial sum_c f^2 per pixel

    // ---------------- pass 1: accumulate p*f and f^2 over my 16 channels ----
#pragma unroll 8
    for (int c = 0; c < 16; c++) {
        const float2 F = *reinterpret_cast<const float2*>(feB + (size_t)c * HWn);
        sf0 = fmaf(F.x, F.x, sf0);
        sf1 = fmaf(F.y, F.y, sf1);
#pragma unroll
        for (int dh = 0; dh < 3; dh++) {
            const int r = h + dh - 1;
            const bool v = (dh == 1) | ((dh == 0) ? up : dn);
            const float* rp = fuB + (size_t)c * HWn + r * Wn;
            float2 P = make_float2(0.f, 0.f);
            if (v) P = *reinterpret_cast<const float2*>(rp);
            float lft = __shfl_up_sync(0xffffffffu, P.y, 1);
            float rgt = __shfl_down_sync(0xffffffffu, P.x, 1);
            if (lEdge) lft = (lIn && v) ? rp[-1] : 0.f;
            if (rEdge) rgt = (rIn && v) ? rp[2]  : 0.f;
            const int kb = dh * 3;
            ax[kb + 0][0] = fmaf(lft, F.x, ax[kb + 0][0]);
            ax[kb + 1][0] = fmaf(P.x, F.x, ax[kb + 1][0]);
            ax[kb + 2][0] = fmaf(P.y, F.x, ax[kb + 2][0]);
            ax[kb + 0][1] = fmaf(P.x, F.y, ax[kb + 0][1]);
            ax[kb + 1][1] = fmaf(P.y, F.y, ax[kb + 1][1]);
            ax[kb + 2][1] = fmaf(rgt, F.y, ax[kb + 2][1]);
        }
    }

    // ---------------- combine partials across the quad ----------------
    {
        float* my = red[wid][lane];
#pragma unroll
        for (int k = 0; k < 9; k++) { my[k * 2] = ax[k][0]; my[k * 2 + 1] = ax[k][1]; }
        my[18] = sf0; my[19] = sf1;
    }
    __syncthreads();
    {
        const int base = wid & ~3;
#pragma unroll
        for (int j = 0; j < 3; j++) {
            const int pw = base + ((half + 1 + j) & 3);   // the other 3 warps
            const float* ot = red[pw][lane];
#pragma unroll
            for (int k = 0; k < 9; k++) { ax[k][0] += ot[k * 2]; ax[k][1] += ot[k * 2 + 1]; }
            sf0 += ot[18]; sf1 += ot[19];
        }
    }

    // ---------------- gather SS at the 9 neighbor positions ----------------
    float ssn[9][2];
    {
        const float* ssB = g_ss + (size_t)b * HWn + w0;
#pragma unroll
        for (int dh = 0; dh < 3; dh++) {
            const int r = h + dh - 1;
            const bool v = (dh == 1) | ((dh == 0) ? up : dn);
            const float* rp = ssB + r * Wn;
            float2 S = make_float2(0.f, 0.f);
            if (v) S = *reinterpret_cast<const float2*>(rp);
            float lft = __shfl_up_sync(0xffffffffu, S.y, 1);
            float rgt = __shfl_down_sync(0xffffffffu, S.x, 1);
            if (lEdge) lft = (lIn && v) ? rp[-1] : 0.f;
            if (rEdge) rgt = (rIn && v) ? rp[2]  : 0.f;
            const int kb = dh * 3;
            ssn[kb + 0][0] = lft; ssn[kb + 1][0] = S.x; ssn[kb + 2][0] = S.y;
            ssn[kb + 0][1] = S.x; ssn[kb + 1][1] = S.y; ssn[kb + 2][1] = rgt;
        }
    }

    // ---------------- softmax weights (stored back into ax) ----------------
#pragma unroll
    for (int px = 0; px < 2; px++) {
        const float sf = px ? sf1 : sf0;
        float d[9];
#pragma unroll
        for (int k = 0; k < 9; k++) {
            float d2 = ssn[k][px] - 2.f * ax[k][px] + sf;
            d[k] = sqrtf(fmaxf(d2, 0.f));
        }
        float mn = d[0];
#pragma unroll
        for (int k = 1; k < 9; k++) mn = fminf(mn, d[k]);
        float s = 0.f;
#pragma unroll
        for (int k = 0; k < 9; k++) {
            float e = __expf(mn - d[k]);
            ax[k][px] = e;
            s += e;
        }
        float inv = 1.f / s;
#pragma unroll
        for (int k = 0; k < 9; k++) ax[k][px] *= inv;
    }

    // ------------- pass 2: weighted neighbor sum + residual (my 16 ch) ------
#pragma unroll 8
    for (int c = 0; c < 16; c++) {
        const float2 F = *reinterpret_cast<const float2*>(feB + (size_t)c * HWn);
        float r0 = F.x, r1 = F.y;
#pragma unroll
        for (int dh = 0; dh < 3; dh++) {
            const int r = h + dh - 1;
            const bool v = (dh == 1) | ((dh == 0) ? up : dn);
            const float* rp = fuB + (size_t)c * HWn + r * Wn;
            float2 P = make_float2(0.f, 0.f);
            if (v) P = *reinterpret_cast<const float2*>(rp);
            float lft = __shfl_up_sync(0xffffffffu, P.y, 1);
            float rgt = __shfl_down_sync(0xffffffffu, P.x, 1);
            if (lEdge) lft = (lIn && v) ? rp[-1] : 0.f;
            if (rEdge) rgt = (rIn && v) ? rp[2]  : 0.f;
            const int kb = dh * 3;
            r0 = fmaf(ax[kb + 0][0], lft, r0);
            r0 = fmaf(ax[kb + 1][0], P.x, r0);
            r0 = fmaf(ax[kb + 2][0], P.y, r0);
            r1 = fmaf(ax[kb + 0][1], P.x, r1);
            r1 = fmaf(ax[kb + 1][1], P.y, r1);
            r1 = fmaf(ax[kb + 2][1], rgt, r1);
        }
        float2 o;
        o.x = r0;
        o.y = r1;
        *reinterpret_cast<float2*>(outB + (size_t)c * HWn) = o;
    }
}

// ---------------------------------------------------------------------------
extern "C" void kernel_launch(void* const* d_in, const int* in_sizes, int n_in,
                              void* d_out, int out_size) {
    const float* fe = (const float*)d_in[0];
    const float* fu = (const float*)d_in[1];
    float* out = (float*)d_out;

    // SS precompute: B*H*W = 131072 pixels
    ss_kernel<<<(Bn * HWn) / 256, 256>>>(fu);
    // main: 2048 pixel-groups x 4 channel-quarters = 8192 warps, 8 warps/block
    refine_kernel<<<1024, 256>>>(fe, fu, out);
}

// round 4
// speedup vs baseline: 1.8097x; 1.8097x over previous
#include <cuda_runtime.h>

// Problem constants
#define Bn 8
#define Cn 64
#define Hn 128
#define Wn 128
#define HWn (Hn * Wn)

// Scratch: per-pixel sum of squares of fused over channels (512 KB)
__device__ float g_ss[Bn * HWn];

// ---------------------------------------------------------------------------
// Kernel 1: SS[b,h,w] = sum_c fused[b,c,h,w]^2
// ---------------------------------------------------------------------------
__global__ __launch_bounds__(256) void ss_kernel(const float* __restrict__ fused) {
    int p = blockIdx.x * blockDim.x + threadIdx.x;      // 0 .. B*HW-1
    int b = p >> 14;
    int pos = p & (HWn - 1);
    const float* ptr = fused + (size_t)b * Cn * HWn + pos;
    float s = 0.f;
#pragma unroll 16
    for (int c = 0; c < Cn; c++) {
        float v = ptr[c * HWn];
        s = fmaf(v, v, s);
    }
    g_ss[p] = s;
}

// ---------------------------------------------------------------------------
// Kernel 2: main refine, 2-way channel split, shuffle-free halo.
// A pair of warps owns 64 consecutive w of one (b,h) row (2 px/thread,
// float2). Warp half=0 accumulates channels [0,32), half=1 channels [32,64).
// The w-halo comes from 3 independent predicated loads per row (all L1/L2
// resident) instead of shfl — no load->shfl serial chains, no MIO traffic.
// ---------------------------------------------------------------------------
__global__ __launch_bounds__(256) void refine_kernel(const float* __restrict__ fe,
                                                     const float* __restrict__ fused,
                                                     float* __restrict__ out) {
    __shared__ float red[8][32][21];   // [warp][lane][18 ax + 2 sf], pad 21

    const int lane   = threadIdx.x & 31;
    const int wid    = threadIdx.x >> 5;
    const int pairId = blockIdx.x * 4 + (wid >> 1);  // 0 .. 2047
    const int half   = wid & 1;                       // channel half
    const int seg    = pairId & 1;                    // which 64-wide half row
    const int h      = (pairId >> 1) & (Hn - 1);
    const int b      = pairId >> 8;
    const int w0     = seg * 64 + lane * 2;
    const int c0     = half * 32;

    const size_t bOff = (size_t)b * Cn * HWn;
    const float* feB  = fe    + bOff + (size_t)c0 * HWn + h * Wn + w0;
    const float* fuB  = fused + bOff + (size_t)c0 * HWn + w0;
    float*       outB = out   + bOff + (size_t)c0 * HWn + h * Wn + w0;

    const bool up = (h > 0), dn = (h < Hn - 1);
    // halo pixel validity (image edge only; loop-invariant -> hoisted @P)
    const bool hasL = (w0 > 0);          // pixel w0-1 exists
    const bool hasR = (w0 + 2 < Wn);     // pixel w0+2 exists

    // row validity, one bool per dh (loop-invariant)
    const bool vRow[3] = {up, true, dn};

    // partial cross-correlation accumulators: ax[k][px] = sum_c p_k * f
    float ax[9][2];
#pragma unroll
    for (int k = 0; k < 9; k++) { ax[k][0] = 0.f; ax[k][1] = 0.f; }
    float sf0 = 0.f, sf1 = 0.f;   // partial sum_c f^2 per pixel

    // ---------------- pass 1: accumulate p*f and f^2 over my 32 channels ----
#pragma unroll 8
    for (int c = 0; c < 32; c++) {
        const float2 F = *reinterpret_cast<const float2*>(feB + (size_t)c * HWn);
        sf0 = fmaf(F.x, F.x, sf0);
        sf1 = fmaf(F.y, F.y, sf1);
#pragma unroll
        for (int dh = 0; dh < 3; dh++) {
            const bool v = vRow[dh];
            const float* rp = fuB + (size_t)c * HWn + (h + dh - 1) * Wn;
            float2 P = make_float2(0.f, 0.f);
            if (v) P = *reinterpret_cast<const float2*>(rp);
            const float lft = (v && hasL) ? rp[-1] : 0.f;
            const float rgt = (v && hasR) ? rp[2]  : 0.f;
            const int kb = dh * 3;
            ax[kb + 0][0] = fmaf(lft, F.x, ax[kb + 0][0]);
            ax[kb + 1][0] = fmaf(P.x, F.x, ax[kb + 1][0]);
            ax[kb + 2][0] = fmaf(P.y, F.x, ax[kb + 2][0]);
            ax[kb + 0][1] = fmaf(P.x, F.y, ax[kb + 0][1]);
            ax[kb + 1][1] = fmaf(P.y, F.y, ax[kb + 1][1]);
            ax[kb + 2][1] = fmaf(rgt, F.y, ax[kb + 2][1]);
        }
    }

    // ---------------- combine partials with partner warp ----------------
    {
        float* my = red[wid][lane];
#pragma unroll
        for (int k = 0; k < 9; k++) { my[k * 2] = ax[k][0]; my[k * 2 + 1] = ax[k][1]; }
        my[18] = sf0; my[19] = sf1;
    }
    __syncthreads();
    {
        const float* ot = red[wid ^ 1][lane];
#pragma unroll
        for (int k = 0; k < 9; k++) { ax[k][0] += ot[k * 2]; ax[k][1] += ot[k * 2 + 1]; }
        sf0 += ot[18]; sf1 += ot[19];
    }

    // ---------------- gather SS at the 9 neighbor positions ----------------
    float ssn[9][2];
    {
        const float* ssB = g_ss + (size_t)b * HWn + w0;
#pragma unroll
        for (int dh = 0; dh < 3; dh++) {
            const bool v = vRow[dh];
            const float* rp = ssB + (h + dh - 1) * Wn;
            float2 S = make_float2(0.f, 0.f);
            if (v) S = *reinterpret_cast<const float2*>(rp);
            const float lft = (v && hasL) ? rp[-1] : 0.f;
            const float rgt = (v && hasR) ? rp[2]  : 0.f;
            const int kb = dh * 3;
            ssn[kb + 0][0] = lft; ssn[kb + 1][0] = S.x; ssn[kb + 2][0] = S.y;
            ssn[kb + 0][1] = S.x; ssn[kb + 1][1] = S.y; ssn[kb + 2][1] = rgt;
        }
    }

    // ---------------- softmax weights (stored back into ax) ----------------
#pragma unroll
    for (int px = 0; px < 2; px++) {
        const float sf = px ? sf1 : sf0;
        float d[9];
#pragma unroll
        for (int k = 0; k < 9; k++) {
            float d2 = ssn[k][px] - 2.f * ax[k][px] + sf;
            d[k] = sqrtf(fmaxf(d2, 0.f));
        }
        float mn = d[0];
#pragma unroll
        for (int k = 1; k < 9; k++) mn = fminf(mn, d[k]);
        float s = 0.f;
#pragma unroll
        for (int k = 0; k < 9; k++) {
            float e = __expf(mn - d[k]);
            ax[k][px] = e;
            s += e;
        }
        float inv = 1.f / s;
#pragma unroll
        for (int k = 0; k < 9; k++) ax[k][px] *= inv;
    }

    // ------------- pass 2: weighted neighbor sum + residual (my 32 ch) ------
#pragma unroll 8
    for (int c = 0; c < 32; c++) {
        const float2 F = *reinterpret_cast<const float2*>(feB + (size_t)c * HWn);
        float r0 = F.x, r1 = F.y;
#pragma unroll
        for (int dh = 0; dh < 3; dh++) {
            const bool v = vRow[dh];
            const float* rp = fuB + (size_t)c * HWn + (h + dh - 1) * Wn;
            float2 P = make_float2(0.f, 0.f);
            if (v) P = *reinterpret_cast<const float2*>(rp);
            const float lft = (v && hasL) ? rp[-1] : 0.f;
            const float rgt = (v && hasR) ? rp[2]  : 0.f;
            const int kb = dh * 3;
            r0 = fmaf(ax[kb + 0][0], lft, r0);
            r0 = fmaf(ax[kb + 1][0], P.x, r0);
            r0 = fmaf(ax[kb + 2][0], P.y, r0);
            r1 = fmaf(ax[kb + 0][1], P.x, r1);
            r1 = fmaf(ax[kb + 1][1], P.y, r1);
            r1 = fmaf(ax[kb + 2][1], rgt, r1);
        }
        float2 o;
        o.x = r0;
        o.y = r1;
        *reinterpret_cast<float2*>(outB + (size_t)c * HWn) = o;
    }
}

// ---------------------------------------------------------------------------
extern "C" void kernel_launch(void* const* d_in, const int* in_sizes, int n_in,
                              void* d_out, int out_size) {
    const float* fe = (const float*)d_in[0];
    const float* fu = (const float*)d_in[1];
    float* out = (float*)d_out;

    // SS precompute: B*H*W = 131072 pixels
    ss_kernel<<<(Bn * HWn) / 256, 256>>>(fu);
    // main: 2048 pixel-groups x 2 channel-halves = 4096 warps, 8 warps/block
    refine_kernel<<<512, 256>>>(fe, fu, out);
}